// round 8
// baseline (speedup 1.0000x reference)
#include <cuda_runtime.h>
#include <cuda_bf16.h>
#include <cstdint>

#define GNX 512
#define GNY 512
#define GP (GNX * GNY)            // 262144 pillars
#define GB 4
#define GNPTS 100000
#define GC 64
#define SUB_P 8                   // pillars per subtile (one warp)
#define SUBS_PER_B (GP / SUB_P)   // 32768
#define NSUB (GB * SUBS_PER_B)    // 131072
#define CAP 24                    // bucket capacity per subtile
#define NPTS_TOTAL (GB * GNPTS)   // 400000
#define OVF_MAX 4096

// Buckets: 131072 * 24 entries = 12.6 MB. Cursors zeroed at module load,
// re-zeroed by gather each call. Overflow counter zeroed by spill each call.
__device__ int      g_cursor[NSUB];
__device__ unsigned g_list[(size_t)NSUB * CAP];
__device__ int      g_ovf_cnt;
__device__ uint2    g_ovf[OVF_MAX];

// ---------------------------------------------------------------------------
// K1: fill buckets. 4 points/thread via int4 (4 independent ATOMG chains).
// entry = (pillar & 7) << 20 | global_point_id  (400000 < 2^20).
// Indices are int32 on the wire (JAX x64-off). GNPTS % 4 == 0.
// ---------------------------------------------------------------------------
__global__ void fill_kernel(const int* __restrict__ indices) {
    int t = blockIdx.x * blockDim.x + threadIdx.x;
    if (t >= NPTS_TOTAL / 4) return;
    int b = (t * 4) / GNPTS;
    int4 p4 = reinterpret_cast<const int4*>(indices)[t];
    int base = b * SUBS_PER_B;
    int p[4] = {p4.x, p4.y, p4.z, p4.w};
#pragma unroll
    for (int k = 0; k < 4; k++) {
        if (p[k] >= 0 && p[k] < GP) {
            int sub = base + (p[k] >> 3);
            int pos = atomicAdd(&g_cursor[sub], 1);
            unsigned gid = (unsigned)(t * 4 + k);
            if (pos < CAP) {
                g_list[(size_t)sub * CAP + pos] = ((unsigned)(p[k] & 7) << 20) | gid;
            } else {
                int o = atomicAdd(&g_ovf_cnt, 1);
                if (o < OVF_MAX) g_ovf[o] = make_uint2(gid, (unsigned)p[k]);
            }
        }
    }
}

// ---------------------------------------------------------------------------
// K2: gather. Block = 8 warps; warp = one 8-pillar subtile; lane = (p, j).
// Thread accumulates 16 channels (c = 4j + 16i + m) of its pillar in regs.
// Per entry: 4 matching lanes read the 256B row as 4 x 64B-contiguous
// LDG.128 (__ldcs, read-once). No smem, no atomics, no syncthreads.
// Store: 16 STG.32 per thread; per warp-instr = 4 channel rows x 32B sectors.
// Also re-zeroes its cursor for the next invocation.
// ---------------------------------------------------------------------------
__global__ void __launch_bounds__(256) gather_kernel(const float* __restrict__ x,
                                                     float* __restrict__ out) {
    int warp = threadIdx.x >> 5;
    int lane = threadIdx.x & 31;
    int sub  = blockIdx.x * 8 + warp;
    int myp  = lane >> 2;      // pillar within subtile
    int j    = lane & 3;

    int cnt = g_cursor[sub];
    if (lane == 0) g_cursor[sub] = 0;      // free re-zero for next replay
    cnt = min(cnt, CAP);

    float a[16];
#pragma unroll
    for (int i = 0; i < 16; i++) a[i] = 0.0f;

    const unsigned* lst = g_list + (size_t)sub * CAP;
    for (int e = 0; e < cnt; e++) {
        unsigned ent = __ldg(lst + e);     // uniform within warp (L1 hit)
        if ((int)(ent >> 20) == myp) {
            const float4* row = reinterpret_cast<const float4*>(
                x + (size_t)(ent & 0xFFFFFu) * GC);
#pragma unroll
            for (int i = 0; i < 4; i++) {
                float4 v = __ldcs(row + j + 4 * i);   // lanes j=0..3: 64B contig
                a[4 * i + 0] += v.x;
                a[4 * i + 1] += v.y;
                a[4 * i + 2] += v.z;
                a[4 * i + 3] += v.w;
            }
        }
    }

    int b = sub >> 15;                      // sub / SUBS_PER_B
    int p = ((sub & (SUBS_PER_B - 1)) << 3) + myp;
    float* obase = out + (size_t)b * GC * GP + p;
#pragma unroll
    for (int i = 0; i < 4; i++) {
#pragma unroll
        for (int m = 0; m < 4; m++) {
            int c = 4 * j + 16 * i + m;
            __stwt(obase + (size_t)c * GP, a[4 * i + m]);
        }
    }
}

// ---------------------------------------------------------------------------
// K3: spill — handle bucket overflow (normally zero entries). Single block.
// Runs after gather, so atomicAdd into the already-written out is correct.
// Zeroes the overflow counter for the next invocation.
// ---------------------------------------------------------------------------
__global__ void spill_kernel(const float* __restrict__ x,
                             float* __restrict__ out) {
    int cnt = g_ovf_cnt;
    if (cnt > OVF_MAX) cnt = OVF_MAX;
    int tid = threadIdx.x;
    for (int w = tid; w < cnt * 16; w += 256) {
        int e  = w >> 4;
        int c4 = (w & 15) << 2;
        uint2 ent = g_ovf[e];
        unsigned gid = ent.x;
        int p = (int)ent.y;
        int b = gid / GNPTS;
        float4 v = *reinterpret_cast<const float4*>(x + (size_t)gid * GC + c4);
        float* o = out + ((size_t)b * GC + c4) * GP + p;
        atomicAdd(o + 0 * (size_t)GP, v.x);
        atomicAdd(o + 1 * (size_t)GP, v.y);
        atomicAdd(o + 2 * (size_t)GP, v.z);
        atomicAdd(o + 3 * (size_t)GP, v.w);
    }
    __syncthreads();
    if (tid == 0) g_ovf_cnt = 0;
}

extern "C" void kernel_launch(void* const* d_in, const int* in_sizes, int n_in,
                              void* d_out, int out_size) {
    const float* x   = (const float*)d_in[0];   // (B, N, C) fp32
    const int*   idx = (const int*)d_in[1];     // (B, N) int32
    float*       out = (float*)d_out;           // (B, C, NX, NY) fp32

    (void)in_sizes; (void)n_in; (void)out_size;

    fill_kernel<<<(NPTS_TOTAL / 4 + 255) / 256, 256>>>(idx);
    gather_kernel<<<NSUB / 8, 256>>>(x, out);
    spill_kernel<<<1, 256>>>(x, out);
}

// round 11
// speedup vs baseline: 2.3439x; 2.3439x over previous
#include <cuda_runtime.h>
#include <cuda_bf16.h>
#include <cstdint>

#define GNX 512
#define GNY 512
#define GP (GNX * GNY)            // 262144 pillars
#define GB 4
#define GNPTS 100000
#define GC 64
#define TILE_P 64                 // pillars per tile (one gather block)
#define TILES_PER_B (GP / TILE_P) // 4096
#define NTILES (GB * TILES_PER_B) // 16384
#define CAP 64                    // bucket capacity per tile (mean load 24)
#define NPTS_TOTAL (GB * GNPTS)   // 400000
#define OVF_MAX 4096

// Buckets: 16384 tiles * 64 entries * 4B = 4 MB (L2-resident for gather).
// Cursors zeroed at module load, re-zeroed by gather each call.
// Overflow counter re-zeroed by spill each call.
__device__ int      g_cursor[NTILES];
__device__ unsigned g_list[(size_t)NTILES * CAP];
__device__ int      g_ovf_cnt;
__device__ uint2    g_ovf[OVF_MAX];

// ---------------------------------------------------------------------------
// K1: fill buckets. 4 points/thread via int4 (4 independent ATOMG chains).
// entry = (pillar & 63) << 20 | global_point_id  (400000 < 2^20).
// Indices are int32 on the wire (JAX x64-off). GNPTS % 4 == 0.
// ---------------------------------------------------------------------------
__global__ void fill_kernel(const int* __restrict__ indices) {
    int t = blockIdx.x * blockDim.x + threadIdx.x;
    if (t >= NPTS_TOTAL / 4) return;
    int b = (t * 4) / GNPTS;
    int4 p4 = reinterpret_cast<const int4*>(indices)[t];
    int base = b * TILES_PER_B;
    int p[4] = {p4.x, p4.y, p4.z, p4.w};
#pragma unroll
    for (int k = 0; k < 4; k++) {
        if (p[k] >= 0 && p[k] < GP) {
            int tile = base + (p[k] >> 6);
            int pos = atomicAdd(&g_cursor[tile], 1);
            unsigned gid = (unsigned)(t * 4 + k);
            if (pos < CAP) {
                g_list[(size_t)tile * CAP + pos] =
                    ((unsigned)(p[k] & 63) << 20) | gid;
            } else {
                int o = atomicAdd(&g_ovf_cnt, 1);
                if (o < OVF_MAX) g_ovf[o] = make_uint2(gid, (unsigned)p[k]);
            }
        }
    }
}

// ---------------------------------------------------------------------------
// K2: gather + accumulate + write. One block per 64-pillar tile.
// All threads read the cursor, then a BARRIER, then thread 0 zeroes it —
// the barrier is load-bearing (without it warp 0 can zero the cursor before
// other warps read it, dropping their entries; R10's bug).
// Half-warp per point: 16 lanes read the 256B feature row as float4 (__ldcs,
// read-once, full sectors), 4 smem atomicAdds each; 2 points per warp-iter.
// Then stream the 16 KB (64c x 64p) tile to out with __stwt, coalesced.
// ---------------------------------------------------------------------------
__global__ void __launch_bounds__(256) gather_kernel(const float* __restrict__ x,
                                                     float* __restrict__ out) {
    __shared__ float acc[GC][TILE_P + 1];

    int tid  = threadIdx.x;
    int tile = blockIdx.x;

    int cnt = g_cursor[tile];              // block-wide read
    for (int i = tid; i < GC * (TILE_P + 1); i += 256)
        ((float*)acc)[i] = 0.0f;
    __syncthreads();                       // all reads done before the zero
    if (tid == 0) g_cursor[tile] = 0;      // re-zero for next replay
    cnt = min(cnt, CAP);

    int wid  = tid >> 5;
    int lane = tid & 31;
    int half = lane >> 4;        // which point of the pair
    int lh   = lane & 15;        // lane within half-warp

    const unsigned* lst = g_list + (size_t)tile * CAP;
    for (int e0 = wid * 2; e0 < cnt; e0 += 16) {
        int e = e0 + half;
        if (e < cnt) {
            unsigned ent = lst[e];
            unsigned gid = ent & 0xFFFFFu;
            unsigned plo = ent >> 20;
            float4 v = __ldcs(reinterpret_cast<const float4*>(
                                  x + (size_t)gid * GC) + lh);
            atomicAdd(&acc[4 * lh + 0][plo], v.x);
            atomicAdd(&acc[4 * lh + 1][plo], v.y);
            atomicAdd(&acc[4 * lh + 2][plo], v.z);
            atomicAdd(&acc[4 * lh + 3][plo], v.w);
        }
    }
    __syncthreads();

    int b  = tile / TILES_PER_B;
    int p0 = (tile % TILES_PER_B) << 6;
    float* obase = out + ((size_t)b * GC) * GP + p0;

    for (int i = tid; i < GC * (TILE_P / 4); i += 256) {
        int c = i >> 4;
        int q = (i & 15) << 2;
        float4 v = make_float4(acc[c][q], acc[c][q + 1],
                               acc[c][q + 2], acc[c][q + 3]);
        __stwt(reinterpret_cast<float4*>(obase + (size_t)c * GP + q), v);
    }
}

// ---------------------------------------------------------------------------
// K3: spill — bucket overflow (normally zero entries). Single block, runs
// after gather so atomicAdd into the already-written out is correct.
// Re-zeroes the overflow counter for the next invocation.
// ---------------------------------------------------------------------------
__global__ void spill_kernel(const float* __restrict__ x,
                             float* __restrict__ out) {
    int cnt = g_ovf_cnt;
    if (cnt > OVF_MAX) cnt = OVF_MAX;
    int tid = threadIdx.x;
    for (int w = tid; w < cnt * 16; w += 256) {
        int e  = w >> 4;
        int c4 = (w & 15) << 2;
        uint2 ent = g_ovf[e];
        unsigned gid = ent.x;
        int p = (int)ent.y;
        int b = gid / GNPTS;
        float4 v = *reinterpret_cast<const float4*>(x + (size_t)gid * GC + c4);
        float* o = out + ((size_t)b * GC + c4) * GP + p;
        atomicAdd(o + 0 * (size_t)GP, v.x);
        atomicAdd(o + 1 * (size_t)GP, v.y);
        atomicAdd(o + 2 * (size_t)GP, v.z);
        atomicAdd(o + 3 * (size_t)GP, v.w);
    }
    __syncthreads();
    if (tid == 0) g_ovf_cnt = 0;
}

extern "C" void kernel_launch(void* const* d_in, const int* in_sizes, int n_in,
                              void* d_out, int out_size) {
    const float* x   = (const float*)d_in[0];   // (B, N, C) fp32
    const int*   idx = (const int*)d_in[1];     // (B, N) int32
    float*       out = (float*)d_out;           // (B, C, NX, NY) fp32

    (void)in_sizes; (void)n_in; (void)out_size;

    fill_kernel<<<(NPTS_TOTAL / 4 + 255) / 256, 256>>>(idx);
    gather_kernel<<<NTILES, 256>>>(x, out);
    spill_kernel<<<1, 256>>>(x, out);
}